// round 10
// baseline (speedup 1.0000x reference)
#include <cuda_runtime.h>
#include <math.h>

// ---------------------------------------------------------------------------
// DCWTv2InferenceCache: segment-tree cover-set attention decode step.
// Graph fork/join with a correct residency budget:
//   main : memset d_out -> [fork] -> memset g_f,g_ctr -> partial (1164 blocks,
//          DYNAMIC work-stealing; leaves >=52 block slots free) ->
//          [wait ePrep] -> big_kernel -> [wait eIndep]
//   side : prep_kernel (g_qd/g_scale for big nodes, tiny) -> [ePrep] ->
//          indep_kernel (local window + small nodes, 256-thr blocks that fit
//          the reserved slots, overlapped with the stream) -> [eIndep]
// ---------------------------------------------------------------------------

#define TOKDIM   1024            // 16 heads * 64 dims
#define HEADS    16
#define HDIM     64
#define MAXBIG   16
#define MAXNODES 40
#define GRID_P   1164            // 152*8 - 52 reserved slots for indep
#define BATCH    16              // units per dynamic grab

__device__ float g_f[(size_t)MAXBIG * 64 * TOKDIM];
__device__ float g_qd[MAXBIG * HEADS * HDIM];
__device__ float g_scale[MAXBIG];
__device__ unsigned int g_ctr;

struct PartParams {
    int  nBig;
    int  a[MAXBIG];              // token offset of node
    int  C[MAXBIG];              // chunks (of 64 tokens) in node
    float inv[MAXBIG];           // 1/C
    long unitBase[MAXBIG + 1];   // prefix of C[n]*64 units
};

struct IndepParams {
    int   nSmall;
    int   sdepth[MAXNODES];
    int   sK[MAXNODES];
    int   soff[MAXNODES];        // token offset in V
    int   nBig;
    int   bdepth[MAXBIG];
    float inv_n;
};

// ---- prep: big-node qd/scale (runs first on side stream, ~2us) -------------
__global__ void __launch_bounds__(256) prep_kernel(
    const float* __restrict__ q,
    const float* __restrict__ W,
    const float* __restrict__ temp,
    IndepParams P)
{
    const int bi  = blockIdx.x;
    const int tid = threadIdx.x;
    const int depth = P.bdepth[bi];

    __shared__ float fW[64 * 65];
    __shared__ float q_sh[HEADS * HDIM];

    for (int i = tid; i < HEADS * HDIM; i += 256) q_sh[i] = q[i];
    const float* Wd = W + (long)depth * HDIM * HDIM;
    #pragma unroll
    for (int i = tid; i < HDIM * HDIM; i += 256) {
        int d = i >> 6, e = i & 63;
        fW[e * 65 + d] = Wd[i];              // coalesced load, transposed store
    }
    if (tid == 0) {
        float t  = temp[depth];
        float sp = log1pf(expf(t));          // softplus
        g_scale[bi] = 1.0f / ((sp + 1e-6f) * 8.0f);
    }
    __syncthreads();

    #pragma unroll
    for (int idx = tid; idx < HEADS * HDIM; idx += 256) {
        int h = idx >> 6, d = idx & 63;
        float acc = q_sh[h * HDIM + d];
        #pragma unroll
        for (int e = 0; e < HDIM; e++)
            acc += q_sh[h * HDIM + e] * fW[e * 65 + d];
        g_qd[bi * HEADS * HDIM + idx] = acc;
    }
}

// ---- partial: dynamic work-stealing chunk means -> red into g_f ------------
__global__ void __launch_bounds__(256) partial_kernel(
    const float* __restrict__ V, PartParams P, long U)
{
    const int tid = threadIdx.x;
    __shared__ unsigned int sh_u;

    for (;;) {
        if (tid == 0) sh_u = atomicAdd(&g_ctr, BATCH);
        __syncthreads();
        long u = (long)sh_u;
        if (u >= U) return;
        long u1 = u + BATCH; if (u1 > U) u1 = U;
        __syncthreads();            // protect sh_u before next grab

        while (u < u1) {
            int n = 0;
            while (u >= P.unitBase[n + 1]) n++;
            long rem = u - P.unitBase[n];
            int  k   = (int)(rem / P.C[n]);
            int  c   = (int)(rem % P.C[n]);
            long run = P.C[n] - c;
            if (run > u1 - u) run = u1 - u;

            const float4* p = (const float4*)(V + ((long)P.a[n] + (long)c * 64 + k) * TOKDIM) + tid;
            const long STR = 64L * TOKDIM / 4;

            float4 a0 = {0,0,0,0}, a1 = {0,0,0,0}, a2 = {0,0,0,0}, a3 = {0,0,0,0};
            long r = 0;
            for (; r + 8 <= run; r += 8) {
                float4 x0 = p[0];
                float4 x1 = p[STR];
                float4 x2 = p[2 * STR];
                float4 x3 = p[3 * STR];
                float4 x4 = p[4 * STR];
                float4 x5 = p[5 * STR];
                float4 x6 = p[6 * STR];
                float4 x7 = p[7 * STR];
                a0.x += x0.x; a0.y += x0.y; a0.z += x0.z; a0.w += x0.w;
                a1.x += x1.x; a1.y += x1.y; a1.z += x1.z; a1.w += x1.w;
                a2.x += x2.x; a2.y += x2.y; a2.z += x2.z; a2.w += x2.w;
                a3.x += x3.x; a3.y += x3.y; a3.z += x3.z; a3.w += x3.w;
                a0.x += x4.x; a0.y += x4.y; a0.z += x4.z; a0.w += x4.w;
                a1.x += x5.x; a1.y += x5.y; a1.z += x5.z; a1.w += x5.w;
                a2.x += x6.x; a2.y += x6.y; a2.z += x6.z; a2.w += x6.w;
                a3.x += x7.x; a3.y += x7.y; a3.z += x7.z; a3.w += x7.w;
                p += 8 * STR;
            }
            for (; r < run; r++) {
                float4 x0 = p[0];
                a0.x += x0.x; a0.y += x0.y; a0.z += x0.z; a0.w += x0.w;
                p += STR;
            }
            float s = P.inv[n];
            float* o = g_f + ((long)n * 64 + k) * TOKDIM + tid * 4;
            atomicAdd(o + 0, ((a0.x + a1.x) + (a2.x + a3.x)) * s);
            atomicAdd(o + 1, ((a0.y + a1.y) + (a2.y + a3.y)) * s);
            atomicAdd(o + 2, ((a0.z + a1.z) + (a2.z + a3.z)) * s);
            atomicAdd(o + 3, ((a0.w + a1.w) + (a2.w + a3.w)) * s);
            u += run;
        }
    }
}

// ---- indep: local window + small nodes (256-thr blocks, fit reserved slots) -
__global__ void __launch_bounds__(256) indep_kernel(
    const float* __restrict__ V,
    const float* __restrict__ q,
    const float* __restrict__ W,
    const float* __restrict__ temp,
    IndepParams P, int pos, float* __restrict__ out)
{
    const int b   = blockIdx.x;
    const int tid = threadIdx.x;

    __shared__ float fW[64 * 65];
    __shared__ float s_sh[512];
    __shared__ float red[256];
    __shared__ float q_sh[HDIM];
    __shared__ float qd[HDIM];
    __shared__ float s_scale, s_mx, s_sum;

    if (b < HEADS) {
        // ================= local-window attention =================
        const int h    = b;
        const int nloc = pos < 512 ? pos : 512;
        const int base = pos - nloc;

        if (tid < HDIM) q_sh[tid] = q[h * HDIM + tid];
        s_sh[tid]       = -1e30f;
        s_sh[tid + 256] = -1e30f;
        __syncthreads();

        // per-thread scores, 2 tokens per thread, 16 float4 in flight each
        for (int t = tid; t < nloc; t += 256) {
            const float4* vp = (const float4*)(V + (long)(base + t) * TOKDIM + h * HDIM);
            const float4* qp = (const float4*)q_sh;
            float acc = 0.f;
            #pragma unroll
            for (int i = 0; i < 16; i++) {
                float4 x  = vp[i];
                float4 qq = qp[i];
                acc += x.x * qq.x + x.y * qq.y + x.z * qq.z + x.w * qq.w;
            }
            s_sh[t] = acc * 0.125f;            // 1/sqrt(64)
        }
        __syncthreads();

        red[tid] = fmaxf(s_sh[tid], s_sh[tid + 256]);
        __syncthreads();
        #pragma unroll
        for (int st = 128; st >= 32; st >>= 1) {
            if (tid < st) red[tid] = fmaxf(red[tid], red[tid + st]);
            __syncthreads();
        }
        if (tid < 32) {
            float m = red[tid];
            #pragma unroll
            for (int o = 16; o > 0; o >>= 1)
                m = fmaxf(m, __shfl_xor_sync(0xffffffff, m, o));
            if (tid == 0) s_mx = m;
        }
        __syncthreads();

        float lsum = 0.f;
        #pragma unroll
        for (int t = tid; t < 512; t += 256) {
            float e = (t < nloc) ? expf(s_sh[t] - s_mx) : 0.f;
            s_sh[t] = e;
            lsum += e;
        }
        red[tid] = lsum;
        __syncthreads();
        #pragma unroll
        for (int st = 128; st >= 32; st >>= 1) {
            if (tid < st) red[tid] += red[tid + st];
            __syncthreads();
        }
        if (tid < 32) {
            float sm = red[tid];
            #pragma unroll
            for (int o = 16; o > 0; o >>= 1)
                sm += __shfl_xor_sync(0xffffffff, sm, o);
            if (tid == 0) s_sum = sm;
        }
        __syncthreads();

        {
            int g = tid >> 6, d = tid & 63;
            float acc = 0.f;
            #pragma unroll 8
            for (int k = g; k < nloc; k += 4)
                acc += s_sh[k] * V[(long)(base + k) * TOKDIM + h * HDIM + d];
            red[tid] = acc;
        }
        __syncthreads();
        if (tid < HDIM) {
            float o = (red[tid] + red[64 + tid]) + (red[128 + tid] + red[192 + tid]);
            atomicAdd(out + h * HDIM + tid, (s_sum > 0.f) ? (o / s_sum) : 0.f);
        }
    } else {
        // ================= small cover-set node attention =================
        const int si    = (b - HEADS) >> 4;
        const int h     = (b - HEADS) & 15;
        const int depth = P.sdepth[si];
        const int K     = P.sK[si];

        if (tid < HDIM) q_sh[tid] = q[h * HDIM + tid];

        const float* Wd = W + (long)depth * HDIM * HDIM;
        #pragma unroll
        for (int i = tid; i < HDIM * HDIM; i += 256) {
            int d = i >> 6, e = i & 63;
            fW[e * 65 + d] = Wd[i];            // transposed, coalesced
        }
        if (tid == 0) {
            float t  = temp[depth];
            float sp = log1pf(expf(t));
            s_scale  = 1.0f / ((sp + 1e-6f) * 8.0f);
        }
        __syncthreads();

        if (tid < HDIM) {
            float acc = q_sh[tid];
            #pragma unroll
            for (int e = 0; e < HDIM; e++) acc += q_sh[e] * fW[e * 65 + tid];
            qd[tid] = acc;
        }
        __syncthreads();

        const float* fsrc = V + (long)P.soff[si] * TOKDIM;
        for (int i = tid; i < K * HDIM; i += 256) {
            int k = i >> 6, d = i & 63;
            fW[k * 65 + d] = fsrc[(long)k * TOKDIM + h * HDIM + d];
        }
        __syncthreads();

        float sc = -1e30f;
        if (tid < K) {
            float acc = 0.f;
            #pragma unroll
            for (int d = 0; d < HDIM; d++) acc += qd[d] * fW[tid * 65 + d];
            sc = acc * s_scale;
        }
        if (tid < 64) red[tid] = sc;
        __syncthreads();
        if (tid < 32) {
            float m = fmaxf(red[tid], red[tid + 32]);
            #pragma unroll
            for (int o = 16; o > 0; o >>= 1)
                m = fmaxf(m, __shfl_xor_sync(0xffffffff, m, o));
            if (tid == 0) s_mx = m;
        }
        __syncthreads();

        float e = (tid < K) ? expf(sc - s_mx) : 0.f;
        if (tid < 64) { s_sh[tid] = e; red[tid] = e; }
        __syncthreads();
        if (tid < 32) {
            float sm = red[tid] + red[tid + 32];
            #pragma unroll
            for (int o = 16; o > 0; o >>= 1)
                sm += __shfl_xor_sync(0xffffffff, sm, o);
            if (tid == 0) s_sum = sm;
        }
        __syncthreads();

        {
            int g = tid >> 6, d = tid & 63;
            float acc = 0.f;
            for (int k = g; k < K; k += 4) acc += s_sh[k] * fW[k * 65 + d];
            red[tid] = acc;
        }
        __syncthreads();
        if (tid < HDIM) {
            float o = (red[tid] + red[64 + tid]) + (red[128 + tid] + red[192 + tid]);
            atomicAdd(out + h * HDIM + tid, (o / s_sum) * P.inv_n);
        }
    }
}

// ---- big-node attention: pure L2 (g_f + g_qd), K=64 always -----------------
__global__ void __launch_bounds__(256) big_kernel(
    IndepParams P, float* __restrict__ out)
{
    const int bi  = blockIdx.x >> 4;
    const int h   = blockIdx.x & 15;
    const int tid = threadIdx.x;

    __shared__ float f_sh[64 * 65];
    __shared__ float qd_sh[HDIM];
    __shared__ float s_sh[64];
    __shared__ float red[256];
    __shared__ float s_mx, s_sum;

    if (tid < HDIM) qd_sh[tid] = g_qd[bi * HEADS * HDIM + h * HDIM + tid];

    const float* fsrc = g_f + (long)bi * 64 * TOKDIM;
    for (int i = tid; i < 64 * HDIM; i += 256) {
        int k = i >> 6, d = i & 63;
        f_sh[k * 65 + d] = fsrc[(long)k * TOKDIM + h * HDIM + d];
    }
    __syncthreads();

    float sc = -1e30f;
    if (tid < 64) {
        float acc = 0.f;
        #pragma unroll
        for (int d = 0; d < HDIM; d++) acc += qd_sh[d] * f_sh[tid * 65 + d];
        sc = acc * g_scale[bi];
    }
    if (tid < 64) red[tid] = sc;
    __syncthreads();
    if (tid < 32) {
        float m = fmaxf(red[tid], red[tid + 32]);
        #pragma unroll
        for (int o = 16; o > 0; o >>= 1)
            m = fmaxf(m, __shfl_xor_sync(0xffffffff, m, o));
        if (tid == 0) s_mx = m;
    }
    __syncthreads();

    float e = (tid < 64) ? expf(sc - s_mx) : 0.f;
    if (tid < 64) { s_sh[tid] = e; red[tid] = e; }
    __syncthreads();
    if (tid < 32) {
        float sm = red[tid] + red[tid + 32];
        #pragma unroll
        for (int o = 16; o > 0; o >>= 1)
            sm += __shfl_xor_sync(0xffffffff, sm, o);
        if (tid == 0) s_sum = sm;
    }
    __syncthreads();

    {
        int g = tid >> 6, d = tid & 63;
        float acc = 0.f;
        for (int k = g; k < 64; k += 4) acc += s_sh[k] * f_sh[k * 65 + d];
        red[tid] = acc;
    }
    __syncthreads();
    if (tid < HDIM) {
        float o = (red[tid] + red[64 + tid]) + (red[128 + tid] + red[192 + tid]);
        atomicAdd(out + h * HDIM + tid, (o / s_sum) * P.inv_n);
    }
}

// ---------------------------------------------------------------------------
extern "C" void kernel_launch(void* const* d_in, const int* in_sizes, int n_in,
                              void* d_out, int out_size)
{
    const float* V    = (const float*)d_in[0];
    const float* q    = (const float*)d_in[1];
    const float* W    = (const float*)d_in[2];
    const float* temp = (const float*)d_in[3];

    const int pos = in_sizes[0] / TOKDIM;

    const int  LOG_N      = 17;
    const long LEAF_START = 1L << LOG_N;
    const long MAX_LEN    = 65536;

    PartParams  bp; bp.nBig = 0;
    IndepParams ip; ip.nSmall = 0; ip.nBig = 0;
    int nTotal = 0;

    auto addNode = [&](long idx) {
        int fl = 0; long t = idx;
        while (t > 1) { t >>= 1; fl++; }
        int depth = LOG_N - fl;
        long L = 1L << depth;
        long a = (idx << depth) - LEAF_START;
        nTotal++;
        if (L > 64) {
            int bi = bp.nBig++;
            bp.a[bi]   = (int)a;
            bp.C[bi]   = (int)(L / 64);
            bp.inv[bi] = 1.0f / (float)(L / 64);
            ip.bdepth[ip.nBig++] = depth;
        } else {
            int si = ip.nSmall++;
            ip.sdepth[si] = depth;
            ip.sK[si]     = (int)L;
            ip.soff[si]   = (int)a;
        }
    };

    long l = LEAF_START;
    long r = LEAF_START + (pos < MAX_LEN ? (long)pos : MAX_LEN);
    while (l < r) {
        if (l & 1) { addNode(l); l++; }
        if (r & 1) { r--; addNode(r); }
        l >>= 1; r >>= 1;
    }
    ip.inv_n = nTotal > 0 ? 1.0f / (float)nTotal : 0.f;

    bp.unitBase[0] = 0;
    for (int i = 0; i < bp.nBig; i++)
        bp.unitBase[i + 1] = bp.unitBase[i] + (long)bp.C[i] * 64;
    long U = bp.nBig ? bp.unitBase[bp.nBig] : 0;

    // lazy-init side stream + events (created on the uncaptured correctness call)
    static cudaStream_t s1 = nullptr;
    static cudaEvent_t  eFork = nullptr, ePrep = nullptr, eIndep = nullptr;
    if (!s1) {
        cudaStreamCreateWithFlags(&s1, cudaStreamNonBlocking);
        cudaEventCreateWithFlags(&eFork, cudaEventDisableTiming);
        cudaEventCreateWithFlags(&ePrep, cudaEventDisableTiming);
        cudaEventCreateWithFlags(&eIndep, cudaEventDisableTiming);
    }

    // main: zero output, then fork
    cudaMemsetAsync(d_out, 0, (size_t)out_size * sizeof(float));
    cudaEventRecord(eFork, 0);
    cudaStreamWaitEvent(s1, eFork, 0);

    // side: big-node prep first (tiny), then local + small nodes
    if (bp.nBig > 0)
        prep_kernel<<<bp.nBig, 256, 0, s1>>>(q, W, temp, ip);
    cudaEventRecord(ePrep, s1);
    int gridA = HEADS + ip.nSmall * HEADS;
    indep_kernel<<<gridA, 256, 0, s1>>>(V, q, W, temp, ip, pos, (float*)d_out);
    cudaEventRecord(eIndep, s1);

    // main: HBM stream (dynamic work-stealing; leaves slots for side branch)
    if (bp.nBig > 0) {
        void* gf_ptr = nullptr; void* ctr_ptr = nullptr;
        cudaGetSymbolAddress(&gf_ptr, g_f);
        cudaGetSymbolAddress(&ctr_ptr, g_ctr);
        cudaMemsetAsync(gf_ptr, 0, (size_t)bp.nBig * 64 * TOKDIM * sizeof(float));
        cudaMemsetAsync(ctr_ptr, 0, sizeof(unsigned int));
        partial_kernel<<<GRID_P, 256>>>(V, bp, U);
        // big-node epilogue: needs g_f (same stream) + g_qd/g_scale (ePrep)
        cudaStreamWaitEvent(0, ePrep, 0);
        big_kernel<<<bp.nBig * HEADS, 256>>>(ip, (float*)d_out);
    }

    // final join: indep's contributions to d_out complete before stream end
    cudaStreamWaitEvent(0, eIndep, 0);
}

// round 11
// speedup vs baseline: 1.0937x; 1.0937x over previous
#include <cuda_runtime.h>
#include <math.h>

// ---------------------------------------------------------------------------
// DCWTv2InferenceCache: segment-tree cover-set attention decode step.
// Serial graph (overlap schemes disproven in R5-R10):
//   memset d_out, memset g_f
//   attn1   : local window + small nodes. Local window staged ONCE into a
//             132KB transposed smem tile (pad 515 -> conflict-free both
//             passes); scores + softmax + weighted sum all from smem.
//   partial : R3-proven 1216-block balanced HBM stream (5.5 TB/s).
//   big     : big-node attention from g_f (+ in-block qd), float4 loads.
// ---------------------------------------------------------------------------

#define TOKDIM   1024            // 16 heads * 64 dims
#define HEADS    16
#define HDIM     64
#define MAXBIG   16
#define MAXNODES 40
#define GRID_P   1216            // R3-proven streaming grid
#define TPAD     515             // token-dim pad: bank = (3d + t) % 32
#define DSMEM    (HDIM * TPAD * 4)   // 131,840 B

__device__ float g_f[(size_t)MAXBIG * 64 * TOKDIM];

struct PartParams {
    int  nBig;
    int  a[MAXBIG];              // token offset of node
    int  C[MAXBIG];              // chunks (of 64 tokens) in node
    float inv[MAXBIG];           // 1/C
    long unitBase[MAXBIG + 1];   // prefix of C[n]*64 units
};

struct NodeParams {
    int   nSmall;
    int   sdepth[MAXNODES];
    int   sK[MAXNODES];
    int   soff[MAXNODES];        // token offset in V
    int   nBig;
    int   bdepth[MAXBIG];
    float inv_n;
};

// ---- partial: balanced chunk means -> red into g_f (R3 config, verbatim) ---
__global__ void __launch_bounds__(256) partial_kernel(
    const float* __restrict__ V, PartParams P, long U)
{
    const int tid = threadIdx.x;
    long u  = (long)blockIdx.x       * U / GRID_P;
    long u1 = ((long)blockIdx.x + 1) * U / GRID_P;

    while (u < u1) {
        int n = 0;
        while (u >= P.unitBase[n + 1]) n++;
        long rem = u - P.unitBase[n];
        int  k   = (int)(rem / P.C[n]);
        int  c   = (int)(rem % P.C[n]);
        long run = P.C[n] - c;
        if (run > u1 - u) run = u1 - u;

        const float4* p = (const float4*)(V + ((long)P.a[n] + (long)c * 64 + k) * TOKDIM) + tid;
        const long STR = 64L * TOKDIM / 4;

        float4 a0 = {0,0,0,0}, a1 = {0,0,0,0}, a2 = {0,0,0,0}, a3 = {0,0,0,0};
        long r = 0;
        for (; r + 8 <= run; r += 8) {
            float4 x0 = p[0];
            float4 x1 = p[STR];
            float4 x2 = p[2 * STR];
            float4 x3 = p[3 * STR];
            float4 x4 = p[4 * STR];
            float4 x5 = p[5 * STR];
            float4 x6 = p[6 * STR];
            float4 x7 = p[7 * STR];
            a0.x += x0.x; a0.y += x0.y; a0.z += x0.z; a0.w += x0.w;
            a1.x += x1.x; a1.y += x1.y; a1.z += x1.z; a1.w += x1.w;
            a2.x += x2.x; a2.y += x2.y; a2.z += x2.z; a2.w += x2.w;
            a3.x += x3.x; a3.y += x3.y; a3.z += x3.z; a3.w += x3.w;
            a0.x += x4.x; a0.y += x4.y; a0.z += x4.z; a0.w += x4.w;
            a1.x += x5.x; a1.y += x5.y; a1.z += x5.z; a1.w += x5.w;
            a2.x += x6.x; a2.y += x6.y; a2.z += x6.z; a2.w += x6.w;
            a3.x += x7.x; a3.y += x7.y; a3.z += x7.z; a3.w += x7.w;
            p += 8 * STR;
        }
        for (; r < run; r++) {
            float4 x0 = p[0];
            a0.x += x0.x; a0.y += x0.y; a0.z += x0.z; a0.w += x0.w;
            p += STR;
        }
        float s = P.inv[n];
        float* o = g_f + ((long)n * 64 + k) * TOKDIM + tid * 4;
        atomicAdd(o + 0, ((a0.x + a1.x) + (a2.x + a3.x)) * s);
        atomicAdd(o + 1, ((a0.y + a1.y) + (a2.y + a3.y)) * s);
        atomicAdd(o + 2, ((a0.z + a1.z) + (a2.z + a3.z)) * s);
        atomicAdd(o + 3, ((a0.w + a1.w) + (a2.w + a3.w)) * s);
        u += run;
    }
}

// ---- attn1: local window (smem-tiled) + small nodes ------------------------
// grid = 16 + nSmall*16, block = 256, dynamic smem = DSMEM.
__global__ void __launch_bounds__(256) attn1_kernel(
    const float* __restrict__ V,
    const float* __restrict__ q,
    const float* __restrict__ W,
    const float* __restrict__ temp,
    NodeParams P, int pos, float* __restrict__ out)
{
    extern __shared__ float fbuf[];     // [HDIM][TPAD] transposed tile
    const int b   = blockIdx.x;
    const int tid = threadIdx.x;

    __shared__ float W_sh[64 * 65];
    __shared__ float s_sh[512];
    __shared__ float red[256];
    __shared__ float q_sh[HDIM];
    __shared__ float qd[HDIM];
    __shared__ float s_scale, s_mx, s_sum;

    if (b < HEADS) {
        // ================= local-window attention =================
        const int h    = b;
        const int nloc = pos < 512 ? pos : 512;
        const int base = pos - nloc;

        if (tid < HDIM) q_sh[tid] = q[h * HDIM + tid];
        s_sh[tid]       = -1e30f;
        s_sh[tid + 256] = -1e30f;

        // one burst: whole window -> transposed smem tile (coalesced reads,
        // 2 lines/warp-LDG; scalar stores, banks (3d+t)%32 conflict-free)
        for (int i = tid; i < nloc * 16; i += 256) {
            int t = i >> 4, j = i & 15;
            float4 v = *(const float4*)(V + (long)(base + t) * TOKDIM + h * HDIM + j * 4);
            int d = j * 4;
            fbuf[(d + 0) * TPAD + t] = v.x;
            fbuf[(d + 1) * TPAD + t] = v.y;
            fbuf[(d + 2) * TPAD + t] = v.z;
            fbuf[(d + 3) * TPAD + t] = v.w;
        }
        __syncthreads();

        // scores from smem (lane t -> consecutive addrs, conflict-free)
        for (int t = tid; t < nloc; t += 256) {
            float acc = 0.f;
            #pragma unroll
            for (int d = 0; d < HDIM; d++) acc += q_sh[d] * fbuf[d * TPAD + t];
            s_sh[t] = acc * 0.125f;             // 1/sqrt(64)
        }
        __syncthreads();

        // block max over 512
        red[tid] = fmaxf(s_sh[tid], s_sh[tid + 256]);
        __syncthreads();
        #pragma unroll
        for (int st = 128; st >= 32; st >>= 1) {
            if (tid < st) red[tid] = fmaxf(red[tid], red[tid + st]);
            __syncthreads();
        }
        if (tid < 32) {
            float m = red[tid];
            #pragma unroll
            for (int o = 16; o > 0; o >>= 1)
                m = fmaxf(m, __shfl_xor_sync(0xffffffff, m, o));
            if (tid == 0) s_mx = m;
        }
        __syncthreads();

        // exp + sum
        float lsum = 0.f;
        #pragma unroll
        for (int t = tid; t < 512; t += 256) {
            float e = (t < nloc) ? expf(s_sh[t] - s_mx) : 0.f;
            s_sh[t] = e;
            lsum += e;
        }
        red[tid] = lsum;
        __syncthreads();
        #pragma unroll
        for (int st = 128; st >= 32; st >>= 1) {
            if (tid < st) red[tid] += red[tid + st];
            __syncthreads();
        }
        if (tid < 32) {
            float sm = red[tid];
            #pragma unroll
            for (int o = 16; o > 0; o >>= 1)
                sm += __shfl_xor_sync(0xffffffff, sm, o);
            if (tid == 0) s_sum = sm;
        }
        __syncthreads();

        // weighted sum from smem: 4 k-groups x 64 dims, banks (3d+k) distinct
        {
            int g = tid >> 6, d = tid & 63;
            float acc = 0.f;
            for (int k = g; k < nloc; k += 4)
                acc += s_sh[k] * fbuf[d * TPAD + k];
            red[tid] = acc;
        }
        __syncthreads();
        if (tid < HDIM) {
            float o = (red[tid] + red[64 + tid]) + (red[128 + tid] + red[192 + tid]);
            atomicAdd(out + h * HDIM + tid, (s_sum > 0.f) ? (o / s_sum) : 0.f);
        }
    } else {
        // ================= small cover-set node attention =================
        const int si    = (b - HEADS) >> 4;
        const int h     = (b - HEADS) & 15;
        const int depth = P.sdepth[si];
        const int K     = P.sK[si];

        if (tid < HDIM) q_sh[tid] = q[h * HDIM + tid];

        const float* Wd = W + (long)depth * HDIM * HDIM;
        #pragma unroll
        for (int i = tid; i < HDIM * HDIM; i += 256) {
            int d = i >> 6, e = i & 63;
            W_sh[e * 65 + d] = Wd[i];          // transposed, coalesced
        }
        // f tile [K,64] -> transposed fbuf[d][k]
        const float* fsrc = V + (long)P.soff[si] * TOKDIM;
        for (int i = tid; i < K * HDIM; i += 256) {
            int k = i >> 6, d = i & 63;
            fbuf[d * TPAD + k] = fsrc[(long)k * TOKDIM + h * HDIM + d];
        }
        if (tid == 0) {
            float t  = temp[depth];
            float sp = log1pf(expf(t));        // softplus
            s_scale  = 1.0f / ((sp + 1e-6f) * 8.0f);
        }
        __syncthreads();

        if (tid < HDIM) {
            float acc = q_sh[tid];
            #pragma unroll
            for (int e = 0; e < HDIM; e++) acc += q_sh[e] * W_sh[e * 65 + tid];
            qd[tid] = acc;
        }
        __syncthreads();

        float sc = -1e30f;
        if (tid < K) {
            float acc = 0.f;
            #pragma unroll
            for (int d = 0; d < HDIM; d++) acc += qd[d] * fbuf[d * TPAD + tid];
            sc = acc * s_scale;
        }
        if (tid < 64) red[tid] = sc;
        __syncthreads();
        if (tid < 32) {
            float m = fmaxf(red[tid], red[tid + 32]);
            #pragma unroll
            for (int o = 16; o > 0; o >>= 1)
                m = fmaxf(m, __shfl_xor_sync(0xffffffff, m, o));
            if (tid == 0) s_mx = m;
        }
        __syncthreads();

        float e = (tid < K) ? expf(sc - s_mx) : 0.f;
        if (tid < 64) { s_sh[tid] = e; red[tid] = e; }
        __syncthreads();
        if (tid < 32) {
            float sm = red[tid] + red[tid + 32];
            #pragma unroll
            for (int o = 16; o > 0; o >>= 1)
                sm += __shfl_xor_sync(0xffffffff, sm, o);
            if (tid == 0) s_sum = sm;
        }
        __syncthreads();

        {
            int g = tid >> 6, d = tid & 63;
            float acc = 0.f;
            for (int k = g; k < K; k += 4) acc += s_sh[k] * fbuf[d * TPAD + k];
            red[tid] = acc;
        }
        __syncthreads();
        if (tid < HDIM) {
            float o = (red[tid] + red[64 + tid]) + (red[128 + tid] + red[192 + tid]);
            atomicAdd(out + h * HDIM + tid, (o / s_sum) * P.inv_n);
        }
    }
}

// ---- big: big-node attention from g_f, qd computed in-block -----------------
// grid = nBig*16, block = 256.
__global__ void __launch_bounds__(256) big_kernel(
    const float* __restrict__ q,
    const float* __restrict__ W,
    const float* __restrict__ temp,
    NodeParams P, float* __restrict__ out)
{
    const int bi  = blockIdx.x >> 4;
    const int h   = blockIdx.x & 15;
    const int tid = threadIdx.x;
    const int depth = P.bdepth[bi];

    __shared__ float f_sh[64 * 65];     // f tile [k][d] padded
    __shared__ float W_sh[64 * 65];
    __shared__ float q_sh[HDIM];
    __shared__ float qd[HDIM];
    __shared__ float s_sh[64];
    __shared__ float red[256];
    __shared__ float s_scale, s_mx, s_sum;

    if (tid < HDIM) q_sh[tid] = q[h * HDIM + tid];

    // upfront burst: f tile (float4) + W, independent loads, one round trip
    const float* fsrc = g_f + (long)bi * 64 * TOKDIM + h * HDIM;
    #pragma unroll
    for (int i = tid; i < 64 * 16; i += 256) {      // 64 rows x 16 float4
        int k = i >> 4, j = i & 15;
        float4 v = *(const float4*)(fsrc + (long)k * TOKDIM + j * 4);
        int d = j * 4;
        f_sh[k * 65 + d + 0] = v.x;
        f_sh[k * 65 + d + 1] = v.y;
        f_sh[k * 65 + d + 2] = v.z;
        f_sh[k * 65 + d + 3] = v.w;
    }
    const float* Wd = W + (long)depth * HDIM * HDIM;
    #pragma unroll
    for (int i = tid; i < HDIM * HDIM; i += 256) {
        int d = i >> 6, e = i & 63;
        W_sh[e * 65 + d] = Wd[i];
    }
    if (tid == 0) {
        float t  = temp[depth];
        float sp = log1pf(expf(t));
        s_scale  = 1.0f / ((sp + 1e-6f) * 8.0f);
    }
    __syncthreads();

    if (tid < HDIM) {
        float acc = q_sh[tid];
        #pragma unroll
        for (int e = 0; e < HDIM; e++) acc += q_sh[e] * W_sh[e * 65 + tid];
        qd[tid] = acc;
    }
    __syncthreads();

    float sc = -1e30f;
    if (tid < 64) {
        float acc = 0.f;
        #pragma unroll
        for (int d = 0; d < HDIM; d++) acc += qd[d] * f_sh[tid * 65 + d];
        sc = acc * s_scale;
    }
    if (tid < 64) red[tid] = sc;
    __syncthreads();
    if (tid < 32) {
        float m = fmaxf(red[tid], red[tid + 32]);
        #pragma unroll
        for (int o = 16; o > 0; o >>= 1)
            m = fmaxf(m, __shfl_xor_sync(0xffffffff, m, o));
        if (tid == 0) s_mx = m;
    }
    __syncthreads();

    float e = (tid < 64) ? expf(sc - s_mx) : 0.f;
    if (tid < 64) { s_sh[tid] = e; red[tid] = e; }
    __syncthreads();
    if (tid < 32) {
        float sm = red[tid] + red[tid + 32];
        #pragma unroll
        for (int o = 16; o > 0; o >>= 1)
            sm += __shfl_xor_sync(0xffffffff, sm, o);
        if (tid == 0) s_sum = sm;
    }
    __syncthreads();

    {
        int g = tid >> 6, d = tid & 63;
        float acc = 0.f;
        for (int k = g; k < 64; k += 4) acc += s_sh[k] * f_sh[k * 65 + d];
        red[tid] = acc;
    }
    __syncthreads();
    if (tid < HDIM) {
        float o = (red[tid] + red[64 + tid]) + (red[128 + tid] + red[192 + tid]);
        atomicAdd(out + h * HDIM + tid, (o / s_sum) * P.inv_n);
    }
}

// ---------------------------------------------------------------------------
extern "C" void kernel_launch(void* const* d_in, const int* in_sizes, int n_in,
                              void* d_out, int out_size)
{
    const float* V    = (const float*)d_in[0];
    const float* q    = (const float*)d_in[1];
    const float* W    = (const float*)d_in[2];
    const float* temp = (const float*)d_in[3];

    const int pos = in_sizes[0] / TOKDIM;

    const int  LOG_N      = 17;
    const long LEAF_START = 1L << LOG_N;
    const long MAX_LEN    = 65536;

    PartParams bp; bp.nBig = 0;
    NodeParams np; np.nSmall = 0; np.nBig = 0;
    int nTotal = 0;

    auto addNode = [&](long idx) {
        int fl = 0; long t = idx;
        while (t > 1) { t >>= 1; fl++; }
        int depth = LOG_N - fl;
        long L = 1L << depth;
        long a = (idx << depth) - LEAF_START;
        nTotal++;
        if (L > 64) {
            int bi = bp.nBig++;
            bp.a[bi]   = (int)a;
            bp.C[bi]   = (int)(L / 64);
            bp.inv[bi] = 1.0f / (float)(L / 64);
            np.bdepth[np.nBig++] = depth;
        } else {
            int si = np.nSmall++;
            np.sdepth[si] = depth;
            np.sK[si]     = (int)L;
            np.soff[si]   = (int)a;
        }
    };

    long l = LEAF_START;
    long r = LEAF_START + (pos < MAX_LEN ? (long)pos : MAX_LEN);
    while (l < r) {
        if (l & 1) { addNode(l); l++; }
        if (r & 1) { r--; addNode(r); }
        l >>= 1; r >>= 1;
    }
    np.inv_n = nTotal > 0 ? 1.0f / (float)nTotal : 0.f;

    bp.unitBase[0] = 0;
    for (int i = 0; i < bp.nBig; i++)
        bp.unitBase[i + 1] = bp.unitBase[i] + (long)bp.C[i] * 64;
    long U = bp.nBig ? bp.unitBase[bp.nBig] : 0;

    // one-time opt-in to 132KB dynamic smem (first call is uncaptured)
    static bool init = false;
    if (!init) {
        cudaFuncSetAttribute(attn1_kernel,
                             cudaFuncAttributeMaxDynamicSharedMemorySize, DSMEM);
        init = true;
    }

    cudaMemsetAsync(d_out, 0, (size_t)out_size * sizeof(float));
    if (bp.nBig > 0) {
        void* gf_ptr = nullptr;
        cudaGetSymbolAddress(&gf_ptr, g_f);
        cudaMemsetAsync(gf_ptr, 0, (size_t)bp.nBig * 64 * TOKDIM * sizeof(float));
    }

    int gridA = HEADS + np.nSmall * HEADS;
    attn1_kernel<<<gridA, 256, DSMEM>>>(V, q, W, temp, np, pos, (float*)d_out);

    if (bp.nBig > 0) {
        partial_kernel<<<GRID_P, 256>>>(V, bp, U);
        big_kernel<<<bp.nBig * HEADS, 256>>>(q, W, temp, np, (float*)d_out);
    }
}

// round 12
// speedup vs baseline: 1.0944x; 1.0006x over previous
#include <cuda_runtime.h>
#include <math.h>

// ---------------------------------------------------------------------------
// DCWTv2InferenceCache: segment-tree cover-set attention decode step.
// R12 = R10's overlap schedule + R11's kernels:
//   main : memset d_out -> [fork] -> memset g_f,g_ctr ->
//          partial (1216 blocks, WORK-STEALING -> displaced blocks just grab
//          fewer batches) -> big (self-contained, float4 bursts) -> [join]
//   side : attn1 (local window via 132KB smem tile + small nodes), launched
//          first so its 48 blocks get SM slots before the stream floods them.
// ---------------------------------------------------------------------------

#define TOKDIM   1024            // 16 heads * 64 dims
#define HEADS    16
#define HDIM     64
#define MAXBIG   16
#define MAXNODES 40
#define GRID_P   1216
#define BATCH    16              // units per dynamic grab
#define TPAD     515             // token-dim pad: bank = (3d + t) % 32
#define DSMEM    (HDIM * TPAD * 4)   // 131,840 B

__device__ float g_f[(size_t)MAXBIG * 64 * TOKDIM];
__device__ unsigned int g_ctr;

struct PartParams {
    int  nBig;
    int  a[MAXBIG];              // token offset of node
    int  C[MAXBIG];              // chunks (of 64 tokens) in node
    float inv[MAXBIG];           // 1/C
    long unitBase[MAXBIG + 1];   // prefix of C[n]*64 units
};

struct NodeParams {
    int   nSmall;
    int   sdepth[MAXNODES];
    int   sK[MAXNODES];
    int   soff[MAXNODES];        // token offset in V
    int   nBig;
    int   bdepth[MAXBIG];
    float inv_n;
};

// ---- partial: work-stealing chunk means -> red into g_f --------------------
__global__ void __launch_bounds__(256) partial_kernel(
    const float* __restrict__ V, PartParams P, long U)
{
    const int tid = threadIdx.x;
    __shared__ unsigned int sh_u;

    for (;;) {
        if (tid == 0) sh_u = atomicAdd(&g_ctr, BATCH);
        __syncthreads();
        long u = (long)sh_u;
        if (u >= U) return;
        long u1 = u + BATCH; if (u1 > U) u1 = U;
        __syncthreads();            // protect sh_u before next grab

        while (u < u1) {
            int n = 0;
            while (u >= P.unitBase[n + 1]) n++;
            long rem = u - P.unitBase[n];
            int  k   = (int)(rem / P.C[n]);
            int  c   = (int)(rem % P.C[n]);
            long run = P.C[n] - c;
            if (run > u1 - u) run = u1 - u;

            const float4* p = (const float4*)(V + ((long)P.a[n] + (long)c * 64 + k) * TOKDIM) + tid;
            const long STR = 64L * TOKDIM / 4;

            float4 a0 = {0,0,0,0}, a1 = {0,0,0,0}, a2 = {0,0,0,0}, a3 = {0,0,0,0};
            long r = 0;
            for (; r + 8 <= run; r += 8) {
                float4 x0 = p[0];
                float4 x1 = p[STR];
                float4 x2 = p[2 * STR];
                float4 x3 = p[3 * STR];
                float4 x4 = p[4 * STR];
                float4 x5 = p[5 * STR];
                float4 x6 = p[6 * STR];
                float4 x7 = p[7 * STR];
                a0.x += x0.x; a0.y += x0.y; a0.z += x0.z; a0.w += x0.w;
                a1.x += x1.x; a1.y += x1.y; a1.z += x1.z; a1.w += x1.w;
                a2.x += x2.x; a2.y += x2.y; a2.z += x2.z; a2.w += x2.w;
                a3.x += x3.x; a3.y += x3.y; a3.z += x3.z; a3.w += x3.w;
                a0.x += x4.x; a0.y += x4.y; a0.z += x4.z; a0.w += x4.w;
                a1.x += x5.x; a1.y += x5.y; a1.z += x5.z; a1.w += x5.w;
                a2.x += x6.x; a2.y += x6.y; a2.z += x6.z; a2.w += x6.w;
                a3.x += x7.x; a3.y += x7.y; a3.z += x7.z; a3.w += x7.w;
                p += 8 * STR;
            }
            for (; r < run; r++) {
                float4 x0 = p[0];
                a0.x += x0.x; a0.y += x0.y; a0.z += x0.z; a0.w += x0.w;
                p += STR;
            }
            float s = P.inv[n];
            float* o = g_f + ((long)n * 64 + k) * TOKDIM + tid * 4;
            atomicAdd(o + 0, ((a0.x + a1.x) + (a2.x + a3.x)) * s);
            atomicAdd(o + 1, ((a0.y + a1.y) + (a2.y + a3.y)) * s);
            atomicAdd(o + 2, ((a0.z + a1.z) + (a2.z + a3.z)) * s);
            atomicAdd(o + 3, ((a0.w + a1.w) + (a2.w + a3.w)) * s);
            u += run;
        }
    }
}

// ---- attn1: local window (smem-tiled) + small nodes (side stream) ----------
// grid = 16 + nSmall*16, block = 256, dynamic smem = DSMEM.
__global__ void __launch_bounds__(256) attn1_kernel(
    const float* __restrict__ V,
    const float* __restrict__ q,
    const float* __restrict__ W,
    const float* __restrict__ temp,
    NodeParams P, int pos, float* __restrict__ out)
{
    extern __shared__ float fbuf[];     // [HDIM][TPAD] transposed tile
    const int b   = blockIdx.x;
    const int tid = threadIdx.x;

    __shared__ float W_sh[64 * 65];
    __shared__ float s_sh[512];
    __shared__ float red[256];
    __shared__ float q_sh[HDIM];
    __shared__ float qd[HDIM];
    __shared__ float s_scale, s_mx, s_sum;

    if (b < HEADS) {
        // ================= local-window attention =================
        const int h    = b;
        const int nloc = pos < 512 ? pos : 512;
        const int base = pos - nloc;

        if (tid < HDIM) q_sh[tid] = q[h * HDIM + tid];
        s_sh[tid]       = -1e30f;
        s_sh[tid + 256] = -1e30f;

        // one burst: whole window -> transposed smem tile
        for (int i = tid; i < nloc * 16; i += 256) {
            int t = i >> 4, j = i & 15;
            float4 v = *(const float4*)(V + (long)(base + t) * TOKDIM + h * HDIM + j * 4);
            int d = j * 4;
            fbuf[(d + 0) * TPAD + t] = v.x;
            fbuf[(d + 1) * TPAD + t] = v.y;
            fbuf[(d + 2) * TPAD + t] = v.z;
            fbuf[(d + 3) * TPAD + t] = v.w;
        }
        __syncthreads();

        // scores from smem
        for (int t = tid; t < nloc; t += 256) {
            float acc = 0.f;
            #pragma unroll
            for (int d = 0; d < HDIM; d++) acc += q_sh[d] * fbuf[d * TPAD + t];
            s_sh[t] = acc * 0.125f;             // 1/sqrt(64)
        }
        __syncthreads();

        red[tid] = fmaxf(s_sh[tid], s_sh[tid + 256]);
        __syncthreads();
        #pragma unroll
        for (int st = 128; st >= 32; st >>= 1) {
            if (tid < st) red[tid] = fmaxf(red[tid], red[tid + st]);
            __syncthreads();
        }
        if (tid < 32) {
            float m = red[tid];
            #pragma unroll
            for (int o = 16; o > 0; o >>= 1)
                m = fmaxf(m, __shfl_xor_sync(0xffffffff, m, o));
            if (tid == 0) s_mx = m;
        }
        __syncthreads();

        float lsum = 0.f;
        #pragma unroll
        for (int t = tid; t < 512; t += 256) {
            float e = (t < nloc) ? expf(s_sh[t] - s_mx) : 0.f;
            s_sh[t] = e;
            lsum += e;
        }
        red[tid] = lsum;
        __syncthreads();
        #pragma unroll
        for (int st = 128; st >= 32; st >>= 1) {
            if (tid < st) red[tid] += red[tid + st];
            __syncthreads();
        }
        if (tid < 32) {
            float sm = red[tid];
            #pragma unroll
            for (int o = 16; o > 0; o >>= 1)
                sm += __shfl_xor_sync(0xffffffff, sm, o);
            if (tid == 0) s_sum = sm;
        }
        __syncthreads();

        {
            int g = tid >> 6, d = tid & 63;
            float acc = 0.f;
            for (int k = g; k < nloc; k += 4)
                acc += s_sh[k] * fbuf[d * TPAD + k];
            red[tid] = acc;
        }
        __syncthreads();
        if (tid < HDIM) {
            float o = (red[tid] + red[64 + tid]) + (red[128 + tid] + red[192 + tid]);
            atomicAdd(out + h * HDIM + tid, (s_sum > 0.f) ? (o / s_sum) : 0.f);
        }
    } else {
        // ================= small cover-set node attention =================
        const int si    = (b - HEADS) >> 4;
        const int h     = (b - HEADS) & 15;
        const int depth = P.sdepth[si];
        const int K     = P.sK[si];

        if (tid < HDIM) q_sh[tid] = q[h * HDIM + tid];

        const float* Wd = W + (long)depth * HDIM * HDIM;
        #pragma unroll
        for (int i = tid; i < HDIM * HDIM; i += 256) {
            int d = i >> 6, e = i & 63;
            W_sh[e * 65 + d] = Wd[i];          // transposed, coalesced
        }
        const float* fsrc = V + (long)P.soff[si] * TOKDIM;
        for (int i = tid; i < K * HDIM; i += 256) {
            int k = i >> 6, d = i & 63;
            fbuf[d * TPAD + k] = fsrc[(long)k * TOKDIM + h * HDIM + d];
        }
        if (tid == 0) {
            float t  = temp[depth];
            float sp = log1pf(expf(t));        // softplus
            s_scale  = 1.0f / ((sp + 1e-6f) * 8.0f);
        }
        __syncthreads();

        if (tid < HDIM) {
            float acc = q_sh[tid];
            #pragma unroll
            for (int e = 0; e < HDIM; e++) acc += q_sh[e] * W_sh[e * 65 + tid];
            qd[tid] = acc;
        }
        __syncthreads();

        float sc = -1e30f;
        if (tid < K) {
            float acc = 0.f;
            #pragma unroll
            for (int d = 0; d < HDIM; d++) acc += qd[d] * fbuf[d * TPAD + tid];
            sc = acc * s_scale;
        }
        if (tid < 64) red[tid] = sc;
        __syncthreads();
        if (tid < 32) {
            float m = fmaxf(red[tid], red[tid + 32]);
            #pragma unroll
            for (int o = 16; o > 0; o >>= 1)
                m = fmaxf(m, __shfl_xor_sync(0xffffffff, m, o));
            if (tid == 0) s_mx = m;
        }
        __syncthreads();

        float e = (tid < K) ? expf(sc - s_mx) : 0.f;
        if (tid < 64) { s_sh[tid] = e; red[tid] = e; }
        __syncthreads();
        if (tid < 32) {
            float sm = red[tid] + red[tid + 32];
            #pragma unroll
            for (int o = 16; o > 0; o >>= 1)
                sm += __shfl_xor_sync(0xffffffff, sm, o);
            if (tid == 0) s_sum = sm;
        }
        __syncthreads();

        {
            int g = tid >> 6, d = tid & 63;
            float acc = 0.f;
            for (int k = g; k < K; k += 4) acc += s_sh[k] * fbuf[d * TPAD + k];
            red[tid] = acc;
        }
        __syncthreads();
        if (tid < HDIM) {
            float o = (red[tid] + red[64 + tid]) + (red[128 + tid] + red[192 + tid]);
            atomicAdd(out + h * HDIM + tid, (o / s_sum) * P.inv_n);
        }
    }
}

// ---- big: big-node attention from g_f, qd computed in-block -----------------
// grid = nBig*16, block = 256.
__global__ void __launch_bounds__(256) big_kernel(
    const float* __restrict__ q,
    const float* __restrict__ W,
    const float* __restrict__ temp,
    NodeParams P, float* __restrict__ out)
{
    const int bi  = blockIdx.x >> 4;
    const int h   = blockIdx.x & 15;
    const int tid = threadIdx.x;
    const int depth = P.bdepth[bi];

    __shared__ float f_sh[64 * 65];     // f tile [k][d] padded
    __shared__ float W_sh[64 * 65];
    __shared__ float q_sh[HDIM];
    __shared__ float qd[HDIM];
    __shared__ float s_sh[64];
    __shared__ float red[256];
    __shared__ float s_scale, s_mx, s_sum;

    if (tid < HDIM) q_sh[tid] = q[h * HDIM + tid];

    // upfront burst: f tile (float4) + W, independent loads, one round trip
    const float* fsrc = g_f + (long)bi * 64 * TOKDIM + h * HDIM;
    #pragma unroll
    for (int i = tid; i < 64 * 16; i += 256) {      // 64 rows x 16 float4
        int k = i >> 4, j = i & 15;
        float4 v = *(const float4*)(fsrc + (long)k * TOKDIM + j * 4);
        int d = j * 4;
        f_sh[k * 65 + d + 0] = v.x;
        f_sh[k * 65 + d + 1] = v.y;
        f_sh[k * 65 + d + 2] = v.z;
        f_sh[k * 65 + d + 3] = v.w;
    }
    const float* Wd = W + (long)depth * HDIM * HDIM;
    #pragma unroll
    for (int i = tid; i < HDIM * HDIM; i += 256) {
        int d = i >> 6, e = i & 63;
        W_sh[e * 65 + d] = Wd[i];
    }
    if (tid == 0) {
        float t  = temp[depth];
        float sp = log1pf(expf(t));
        s_scale  = 1.0f / ((sp + 1e-6f) * 8.0f);
    }
    __syncthreads();

    if (tid < HDIM) {
        float acc = q_sh[tid];
        #pragma unroll
        for (int e = 0; e < HDIM; e++) acc += q_sh[e] * W_sh[e * 65 + tid];
        qd[tid] = acc;
    }
    __syncthreads();

    float sc = -1e30f;
    if (tid < 64) {
        float acc = 0.f;
        #pragma unroll
        for (int d = 0; d < HDIM; d++) acc += qd[d] * f_sh[tid * 65 + d];
        sc = acc * s_scale;
    }
    if (tid < 64) red[tid] = sc;
    __syncthreads();
    if (tid < 32) {
        float m = fmaxf(red[tid], red[tid + 32]);
        #pragma unroll
        for (int o = 16; o > 0; o >>= 1)
            m = fmaxf(m, __shfl_xor_sync(0xffffffff, m, o));
        if (tid == 0) s_mx = m;
    }
    __syncthreads();

    float e = (tid < 64) ? expf(sc - s_mx) : 0.f;
    if (tid < 64) { s_sh[tid] = e; red[tid] = e; }
    __syncthreads();
    if (tid < 32) {
        float sm = red[tid] + red[tid + 32];
        #pragma unroll
        for (int o = 16; o > 0; o >>= 1)
            sm += __shfl_xor_sync(0xffffffff, sm, o);
        if (tid == 0) s_sum = sm;
    }
    __syncthreads();

    {
        int g = tid >> 6, d = tid & 63;
        float acc = 0.f;
        for (int k = g; k < 64; k += 4) acc += s_sh[k] * f_sh[k * 65 + d];
        red[tid] = acc;
    }
    __syncthreads();
    if (tid < HDIM) {
        float o = (red[tid] + red[64 + tid]) + (red[128 + tid] + red[192 + tid]);
        atomicAdd(out + h * HDIM + tid, (o / s_sum) * P.inv_n);
    }
}

// ---------------------------------------------------------------------------
extern "C" void kernel_launch(void* const* d_in, const int* in_sizes, int n_in,
                              void* d_out, int out_size)
{
    const float* V    = (const float*)d_in[0];
    const float* q    = (const float*)d_in[1];
    const float* W    = (const float*)d_in[2];
    const float* temp = (const float*)d_in[3];

    const int pos = in_sizes[0] / TOKDIM;

    const int  LOG_N      = 17;
    const long LEAF_START = 1L << LOG_N;
    const long MAX_LEN    = 65536;

    PartParams bp; bp.nBig = 0;
    NodeParams np; np.nSmall = 0; np.nBig = 0;
    int nTotal = 0;

    auto addNode = [&](long idx) {
        int fl = 0; long t = idx;
        while (t > 1) { t >>= 1; fl++; }
        int depth = LOG_N - fl;
        long L = 1L << depth;
        long a = (idx << depth) - LEAF_START;
        nTotal++;
        if (L > 64) {
            int bi = bp.nBig++;
            bp.a[bi]   = (int)a;
            bp.C[bi]   = (int)(L / 64);
            bp.inv[bi] = 1.0f / (float)(L / 64);
            np.bdepth[np.nBig++] = depth;
        } else {
            int si = np.nSmall++;
            np.sdepth[si] = depth;
            np.sK[si]     = (int)L;
            np.soff[si]   = (int)a;
        }
    };

    long l = LEAF_START;
    long r = LEAF_START + (pos < MAX_LEN ? (long)pos : MAX_LEN);
    while (l < r) {
        if (l & 1) { addNode(l); l++; }
        if (r & 1) { r--; addNode(r); }
        l >>= 1; r >>= 1;
    }
    np.inv_n = nTotal > 0 ? 1.0f / (float)nTotal : 0.f;

    bp.unitBase[0] = 0;
    for (int i = 0; i < bp.nBig; i++)
        bp.unitBase[i + 1] = bp.unitBase[i] + (long)bp.C[i] * 64;
    long U = bp.nBig ? bp.unitBase[bp.nBig] : 0;

    // one-time init (first call is the uncaptured correctness run)
    static cudaStream_t s1 = nullptr;
    static cudaEvent_t  eFork = nullptr, eIndep = nullptr;
    if (!s1) {
        cudaFuncSetAttribute(attn1_kernel,
                             cudaFuncAttributeMaxDynamicSharedMemorySize, DSMEM);
        cudaStreamCreateWithFlags(&s1, cudaStreamNonBlocking);
        cudaEventCreateWithFlags(&eFork, cudaEventDisableTiming);
        cudaEventCreateWithFlags(&eIndep, cudaEventDisableTiming);
    }

    // main: zero output, then fork
    cudaMemsetAsync(d_out, 0, (size_t)out_size * sizeof(float));
    cudaEventRecord(eFork, 0);
    cudaStreamWaitEvent(s1, eFork, 0);

    // side: local window + small nodes (launched first -> gets SM slots)
    int gridA = HEADS + np.nSmall * HEADS;
    attn1_kernel<<<gridA, 256, DSMEM, s1>>>(V, q, W, temp, np, pos, (float*)d_out);
    cudaEventRecord(eIndep, s1);

    // main: HBM stream (work-stealing) then big-node epilogue
    if (bp.nBig > 0) {
        void* gf_ptr = nullptr; void* ctr_ptr = nullptr;
        cudaGetSymbolAddress(&gf_ptr, g_f);
        cudaGetSymbolAddress(&ctr_ptr, g_ctr);
        cudaMemsetAsync(gf_ptr, 0, (size_t)bp.nBig * 64 * TOKDIM * sizeof(float));
        cudaMemsetAsync(ctr_ptr, 0, sizeof(unsigned int));
        partial_kernel<<<GRID_P, 256>>>(V, bp, U);
        big_kernel<<<bp.nBig * HEADS, 256>>>(q, W, temp, np, (float*)d_out);
    }

    // final join: attn1's contributions complete before graph end
    cudaStreamWaitEvent(0, eIndep, 0);
}